// round 1
// baseline (speedup 1.0000x reference)
#include <cuda_runtime.h>

// Problem constants
#define B_  2
#define H_  16
#define N_  2048
#define C_  1024
#define D_  64      // head dim
#define BM  64      // query tile
#define BN  64      // key tile

// scratch for attention output x in (B, C, N) layout
__device__ float g_x[B_ * C_ * N_];

// ---------------------------------------------------------------------------
// Kernel 1: fused attention (flash style), fp32.
// Grid: (N/BM, H, B), 256 threads. Per CTA: 64 query rows of one (b,h).
// q/k/v element (b,d,h,n) at b*2097152 + d*32768 + h*2048 + n.
// ---------------------------------------------------------------------------
__global__ void __launch_bounds__(256) attn_kernel(
    const float* __restrict__ q,
    const float* __restrict__ k,
    const float* __restrict__ v)
{
    extern __shared__ float smem[];
    float* Qs = smem;            // [64][64]  (d, n)
    float* Ks = Qs + 64 * 64;    // [64][64]  (d, m)
    float* Ps = Ks + 64 * 64;    // [64][64]  (n, m)
    float* Vt = Ps + 64 * 64;    // [64][68]  (m, d) transposed, padded
    const int VS = 68;

    const int b  = blockIdx.z;
    const int h  = blockIdx.y;
    const int n0 = blockIdx.x * BM;
    const int tid = threadIdx.x;
    const int tx = tid & 15;     // 0..15 -> 4 cols (m for S, d for O)
    const int ty = tid >> 4;     // 0..15 -> 4 rows (n)

    const float scale = 0.022097086912079608f;  // 1/sqrt(2048)
    const size_t base = (size_t)b * (C_ * N_) + (size_t)h * N_;
    const float* qb = q + base;
    const float* kb = k + base;
    const float* vb = v + base;

    // Load Q tile (prescaled)
    for (int idx = tid; idx < D_ * BM; idx += 256) {
        int d = idx >> 6, nl = idx & 63;
        Qs[d * 64 + nl] = qb[(size_t)d * (H_ * N_) + n0 + nl] * scale;
    }

    float o[4][4];
    float rmax[4], rsum[4];
#pragma unroll
    for (int i = 0; i < 4; i++) {
        rmax[i] = -1e30f;
        rsum[i] = 0.0f;
#pragma unroll
        for (int j = 0; j < 4; j++) o[i][j] = 0.0f;
    }

    for (int m0 = 0; m0 < N_; m0 += BN) {
        __syncthreads();  // protect Ks/Vt reuse across iterations (and Qs on iter 0)
        for (int idx = tid; idx < D_ * BN; idx += 256) {
            int d = idx >> 6, ml = idx & 63;
            float kv = kb[(size_t)d * (H_ * N_) + m0 + ml];
            float vv = vb[(size_t)d * (H_ * N_) + m0 + ml];
            Ks[d * 64 + ml] = kv;
            Vt[ml * VS + d] = vv;   // transposed store (padded stride)
        }
        __syncthreads();

        // S = Q^T K  (64x64), thread computes 4x4
        float s[4][4];
#pragma unroll
        for (int i = 0; i < 4; i++)
#pragma unroll
            for (int j = 0; j < 4; j++) s[i][j] = 0.0f;

#pragma unroll 8
        for (int d = 0; d < D_; d++) {
            float4 qv = *(const float4*)(Qs + d * 64 + ty * 4);
            float4 kv = *(const float4*)(Ks + d * 64 + tx * 4);
            float qa[4] = {qv.x, qv.y, qv.z, qv.w};
            float ka[4] = {kv.x, kv.y, kv.z, kv.w};
#pragma unroll
            for (int i = 0; i < 4; i++)
#pragma unroll
                for (int j = 0; j < 4; j++)
                    s[i][j] += qa[i] * ka[j];
        }

        // Online softmax, rows shared by the 16-lane tx group
#pragma unroll
        for (int i = 0; i < 4; i++) {
            float mx = fmaxf(fmaxf(s[i][0], s[i][1]), fmaxf(s[i][2], s[i][3]));
#pragma unroll
            for (int off = 8; off > 0; off >>= 1)
                mx = fmaxf(mx, __shfl_xor_sync(0xffffffffu, mx, off));
            float nm = fmaxf(rmax[i], mx);
            float corr = __expf(rmax[i] - nm);
            rmax[i] = nm;
            float sm = 0.0f;
#pragma unroll
            for (int j = 0; j < 4; j++) {
                float p = __expf(s[i][j] - nm);
                s[i][j] = p;
                sm += p;
            }
#pragma unroll
            for (int off = 8; off > 0; off >>= 1)
                sm += __shfl_xor_sync(0xffffffffu, sm, off);
            rsum[i] = rsum[i] * corr + sm;
#pragma unroll
            for (int j = 0; j < 4; j++) o[i][j] *= corr;
            float4 pv = make_float4(s[i][0], s[i][1], s[i][2], s[i][3]);
            *(float4*)(Ps + (ty * 4 + i) * 64 + tx * 4) = pv;
        }
        __syncthreads();  // Ps visible to all

        // O[n][d] += P[n][m] * Vt[m][d]
#pragma unroll 8
        for (int m = 0; m < BN; m++) {
            float4 vv = *(const float4*)(Vt + m * VS + tx * 4);
            float va[4] = {vv.x, vv.y, vv.z, vv.w};
            float p0 = Ps[(ty * 4 + 0) * 64 + m];
            float p1 = Ps[(ty * 4 + 1) * 64 + m];
            float p2 = Ps[(ty * 4 + 2) * 64 + m];
            float p3 = Ps[(ty * 4 + 3) * 64 + m];
#pragma unroll
            for (int j = 0; j < 4; j++) {
                o[0][j] += p0 * va[j];
                o[1][j] += p1 * va[j];
                o[2][j] += p2 * va[j];
                o[3][j] += p3 * va[j];
            }
        }
    }

    // Epilogue: x[b][(d*16+h)][n] = O[n][d] / rsum[n]
    float inv[4];
#pragma unroll
    for (int i = 0; i < 4; i++) inv[i] = 1.0f / rsum[i];

    float* xb = g_x + (size_t)b * (C_ * N_);
#pragma unroll
    for (int j = 0; j < 4; j++) {
        int d = tx * 4 + j;
        int c = d * H_ + h;
        float4 r = make_float4(o[0][j] * inv[0], o[1][j] * inv[1],
                               o[2][j] * inv[2], o[3][j] * inv[3]);
        *(float4*)(xb + (size_t)c * N_ + n0 + ty * 4) = r;  // n contiguous
    }
}

// ---------------------------------------------------------------------------
// Kernel 2: out[b][o][n] = bias[o] + sum_c W[o][c] * x[b][c][n]
// Tiled SGEMM 64x64, k-tile 16, 256 threads, 4x4 per thread.
// ---------------------------------------------------------------------------
__global__ void __launch_bounds__(256) merge_kernel(
    const float* __restrict__ W,
    const float* __restrict__ bias,
    float* __restrict__ out)
{
    __shared__ float Ws[16][68];   // [c][o] transposed, padded
    __shared__ float Xs[16][64];   // [c][n]

    const int b  = blockIdx.z;
    const int n0 = blockIdx.x * 64;
    const int o0 = blockIdx.y * 64;
    const int tid = threadIdx.x;
    const int tx = tid & 15;   // n
    const int ty = tid >> 4;   // o

    const float* xb = g_x + (size_t)b * (C_ * N_);

    float acc[4][4];
#pragma unroll
    for (int i = 0; i < 4; i++)
#pragma unroll
        for (int j = 0; j < 4; j++) acc[i][j] = 0.0f;

    for (int c0 = 0; c0 < C_; c0 += 16) {
        __syncthreads();
        for (int idx = tid; idx < 64 * 16; idx += 256) {
            int ol = idx >> 4, cl = idx & 15;
            Ws[cl][ol] = W[(size_t)(o0 + ol) * C_ + c0 + cl];
        }
        for (int idx = tid; idx < 16 * 64; idx += 256) {
            int cl = idx >> 6, nl = idx & 63;
            Xs[cl][nl] = xb[(size_t)(c0 + cl) * N_ + n0 + nl];
        }
        __syncthreads();

#pragma unroll
        for (int kk = 0; kk < 16; kk++) {
            float4 a  = *(const float4*)&Ws[kk][ty * 4];
            float4 bb = *(const float4*)&Xs[kk][tx * 4];
            float aa[4] = {a.x, a.y, a.z, a.w};
            float bv[4] = {bb.x, bb.y, bb.z, bb.w};
#pragma unroll
            for (int i = 0; i < 4; i++)
#pragma unroll
                for (int j = 0; j < 4; j++)
                    acc[i][j] += aa[i] * bv[j];
        }
    }

#pragma unroll
    for (int i = 0; i < 4; i++) {
        int oo = o0 + ty * 4 + i;
        float bv = bias[oo];
        float4 r = make_float4(acc[i][0] + bv, acc[i][1] + bv,
                               acc[i][2] + bv, acc[i][3] + bv);
        *(float4*)(out + (size_t)b * (C_ * N_) + (size_t)oo * N_ + n0 + tx * 4) = r;
    }
}

// ---------------------------------------------------------------------------
extern "C" void kernel_launch(void* const* d_in, const int* in_sizes, int n_in,
                              void* d_out, int out_size)
{
    const float* q    = (const float*)d_in[0];
    const float* k    = (const float*)d_in[1];
    const float* v    = (const float*)d_in[2];
    const float* W    = (const float*)d_in[3];
    const float* bias = (const float*)d_in[4];
    float* out = (float*)d_out;

    const int smem_attn = (3 * 64 * 64 + 64 * 68) * sizeof(float);  // 66560 B
    cudaFuncSetAttribute(attn_kernel, cudaFuncAttributeMaxDynamicSharedMemorySize, smem_attn);

    dim3 g1(N_ / BM, H_, B_);
    attn_kernel<<<g1, 256, smem_attn>>>(q, k, v);

    dim3 g2(N_ / 64, C_ / 64, B_);
    merge_kernel<<<g2, 256>>>(W, bias, out);
}